// round 10
// baseline (speedup 1.0000x reference)
#include <cuda_runtime.h>
#include <cuda_fp16.h>
#include <math.h>
#include <stdint.h>

#define BSZ   8
#define TLEN  2048
#define CDIM  1024
#define DDIM  1024
#define MTOT  (BSZ * TLEN)   // 16384

// ---------------- scratch (static device globals; no allocs allowed) ----------
__device__ __align__(256) __half g_xk[MTOT * CDIM];
__device__ __align__(256) __half g_xv[MTOT * CDIM];
__device__ __align__(256) __half g_xr[MTOT * CDIM];
__device__ __align__(256) float  g_k [MTOT * DDIM];
__device__ __align__(256) float  g_v [MTOT * DDIM];
__device__ __align__(256) float  g_r [MTOT * DDIM];   // sigmoid(r)
__device__ __align__(256) __half g_rwkv[MTOT * DDIM];
__device__ __align__(256) __half g_Wk[DDIM * CDIM];
__device__ __align__(256) __half g_Wv[DDIM * CDIM];
__device__ __align__(256) __half g_Wr[DDIM * CDIM];
__device__ __align__(256) __half g_Wo[CDIM * DDIM];

// ---------------- helpers ------------------------------------------------------
__device__ __forceinline__ void mma_f16(float c[4], const uint32_t a[4],
                                        uint32_t b0, uint32_t b1) {
    asm volatile(
        "mma.sync.aligned.m16n8k16.row.col.f32.f16.f16.f32 "
        "{%0,%1,%2,%3}, {%4,%5,%6,%7}, {%8,%9}, {%0,%1,%2,%3};"
        : "+f"(c[0]), "+f"(c[1]), "+f"(c[2]), "+f"(c[3])
        : "r"(a[0]), "r"(a[1]), "r"(a[2]), "r"(a[3]), "r"(b0), "r"(b1));
}

__device__ __forceinline__ void cp_async16(uint32_t dst, const void* src) {
    asm volatile("cp.async.cg.shared.global [%0], [%1], 16;" ::"r"(dst), "l"(src));
}

__device__ __forceinline__ void ldsm_x4(uint32_t& r0, uint32_t& r1,
                                        uint32_t& r2, uint32_t& r3, uint32_t addr) {
    asm volatile("ldmatrix.sync.aligned.m8n8.x4.shared.b16 {%0,%1,%2,%3}, [%4];"
                 : "=r"(r0), "=r"(r1), "=r"(r2), "=r"(r3) : "r"(addr));
}

union HalfPack {
    __half2 h[2];
    uint2 u;
};

// ---------------- 0. convert all four weight matrices to fp16 -----------------
__global__ void round_weights(const float* __restrict__ wk, const float* __restrict__ wv,
                              const float* __restrict__ wr, const float* __restrict__ wo)
{
    const int per = (DDIM * CDIM) / 4;        // float4s per weight
    int i = blockIdx.x * blockDim.x + threadIdx.x;
    int sel = i / per;
    int off = i - sel * per;
    const float* s = (sel == 0) ? wk : (sel == 1) ? wv : (sel == 2) ? wr : wo;
    __half* d = (sel == 0) ? g_Wk : (sel == 1) ? g_Wv : (sel == 2) ? g_Wr : g_Wo;
    float4 v = reinterpret_cast<const float4*>(s)[off];
    HalfPack p;
    p.h[0] = __floats2half2_rn(v.x, v.y);
    p.h[1] = __floats2half2_rn(v.z, v.w);
    reinterpret_cast<uint2*>(d)[off] = p.u;
}

// ---------------- 1. time-shift + mixing (fp16 outputs) -----------------------
__global__ void mix_kernel(const float* __restrict__ x,
                           const float* __restrict__ tmk,
                           const float* __restrict__ tmv,
                           const float* __restrict__ tmr)
{
    int idx = blockIdx.x * blockDim.x + threadIdx.x;     // over MTOT * CDIM / 4
    const int c4cnt = CDIM / 4;
    int c4 = idx % c4cnt;
    int m  = idx / c4cnt;
    int t  = m % TLEN;

    float4 xv4 = reinterpret_cast<const float4*>(x)[idx];
    float4 xx4 = (t > 0) ? reinterpret_cast<const float4*>(x)[idx - c4cnt]
                         : make_float4(0.f, 0.f, 0.f, 0.f);
    float4 mk = reinterpret_cast<const float4*>(tmk)[c4];
    float4 mv = reinterpret_cast<const float4*>(tmv)[c4];
    float4 mr = reinterpret_cast<const float4*>(tmr)[c4];

    HalfPack pk, pv, pr;
    pk.h[0] = __floats2half2_rn(xv4.x * mk.x + xx4.x * (1.f - mk.x),
                                xv4.y * mk.y + xx4.y * (1.f - mk.y));
    pk.h[1] = __floats2half2_rn(xv4.z * mk.z + xx4.z * (1.f - mk.z),
                                xv4.w * mk.w + xx4.w * (1.f - mk.w));
    pv.h[0] = __floats2half2_rn(xv4.x * mv.x + xx4.x * (1.f - mv.x),
                                xv4.y * mv.y + xx4.y * (1.f - mv.y));
    pv.h[1] = __floats2half2_rn(xv4.z * mv.z + xx4.z * (1.f - mv.z),
                                xv4.w * mv.w + xx4.w * (1.f - mv.w));
    pr.h[0] = __floats2half2_rn(xv4.x * mr.x + xx4.x * (1.f - mr.x),
                                xv4.y * mr.y + xx4.y * (1.f - mr.y));
    pr.h[1] = __floats2half2_rn(xv4.z * mr.z + xx4.z * (1.f - mr.z),
                                xv4.w * mr.w + xx4.w * (1.f - mr.w));

    reinterpret_cast<uint2*>(g_xk)[idx] = pk.u;
    reinterpret_cast<uint2*>(g_xv)[idx] = pv.u;
    reinterpret_cast<uint2*>(g_xr)[idx] = pr.u;
}

// ---------------- 2. fp16 tensor-core GEMM:  C[M,N] = A[M,K] * B[N,K]^T -------
// 128x128x32 tile, 4 warps (64x64), 3-stage cp.async pipeline,
// XOR-swizzled fp16 smem (64B rows) + ldmatrix.x4 + m16n8k16.
#define STAGE_BYTES 16384   // A 128*64B + B 128*64B
#define NSTAGE 3

__global__ __launch_bounds__(128, 2)
void gemm_f16(const __half* __restrict__ A, const __half* __restrict__ B,
              float* __restrict__ Cf, __half* __restrict__ Ch,
              int M, int N, int K, int act)
{
    extern __shared__ char smc[];
    const int tid  = threadIdx.x;
    const int lane = tid & 31;
    const int wid  = tid >> 5;
    const int wm = (wid >> 1) << 6;     // 0 or 64
    const int wn = (wid & 1) << 6;      // 0 or 64
    const int g  = lane >> 2;           // 0..7
    const int tg = lane & 3;            // 0..3
    const int hi = lane >> 3;           // 0..3
    const int rr = lane & 7;            // 0..7

    // ---- producer: thread owns row `tid` of both tiles (4 x 16B chunks) ----
    const __half* Ag = A + ((((size_t)blockIdx.y) << 7) + tid) * K;
    const __half* Bg = B + ((((size_t)blockIdx.x) << 7) + tid) * K;

    uint32_t sbase = (uint32_t)__cvta_generic_to_shared(smc);
    const uint32_t pswz = (uint32_t)((tid >> 1) & 3);
    uint32_t dA = sbase + (uint32_t)(tid << 6);     // row * 64B
    uint32_t dB = dA + 8192u;

    // ---- ldmatrix per-lane address precompute ----
    // A x4 tiles: (m,kk),(m+8,kk),(m,kk+8),(m+8,kk+8); hi&1->+8 rows, hi>>1->+8 k
    uint32_t aRowOff[4], aLow[4];
    #pragma unroll
    for (int mi = 0; mi < 4; mi++) {
        int row = wm + (mi << 4) + ((hi & 1) << 3) + rr;
        aRowOff[mi] = (uint32_t)(row << 6);
        aLow[mi] = (uint32_t)((row >> 1) & 3);
    }
    const uint32_t aHi = (uint32_t)(hi >> 1);
    // B x4 tiles: (n0,kk),(n0,kk+8),(n0+8,kk),(n0+8,kk+8); hi>>1->+8 rows, hi&1->+8 k
    uint32_t bRowOff[4], bLow[4];
    #pragma unroll
    for (int nj = 0; nj < 4; nj++) {
        int row = wn + (nj << 4) + ((hi >> 1) << 3) + rr;
        bRowOff[nj] = (uint32_t)(row << 6);
        bLow[nj] = (uint32_t)((row >> 1) & 3);
    }
    const uint32_t bHi = (uint32_t)(hi & 1);

    float acc[4][8][4];
    #pragma unroll
    for (int i = 0; i < 4; i++)
        #pragma unroll
        for (int j = 0; j < 8; j++)
            #pragma unroll
            for (int l = 0; l < 4; l++) acc[i][j][l] = 0.f;

    const int kIters = K >> 5;

#define ISSUEH(IT, S)                                                         \
    {                                                                         \
        uint32_t offS = (uint32_t)((S) * STAGE_BYTES);                        \
        const __half* ap = Ag + (size_t)(IT) * 32;                            \
        const __half* bp = Bg + (size_t)(IT) * 32;                            \
        _Pragma("unroll")                                                     \
        for (int c = 0; c < 4; c++) {                                         \
            cp_async16(dA + offS + (((uint32_t)c ^ pswz) << 4), ap + (c << 3)); \
            cp_async16(dB + offS + (((uint32_t)c ^ pswz) << 4), bp + (c << 3)); \
        }                                                                     \
        asm volatile("cp.async.commit_group;" ::);                            \
    }

    ISSUEH(0, 0);
    if (kIters > 1) ISSUEH(1, 1);

    int stage = 0;
    for (int it = 0; it < kIters; ++it) {
        if (it + 2 < kIters) {
            int s2 = it + 2; int st2 = s2 - (s2 / NSTAGE) * NSTAGE;
            ISSUEH(s2, st2);
            asm volatile("cp.async.wait_group 2;" ::);
        } else if (it + 1 < kIters) {
            asm volatile("cp.async.wait_group 1;" ::);
        } else {
            asm volatile("cp.async.wait_group 0;" ::);
        }
        __syncthreads();

        uint32_t sA = sbase + (uint32_t)(stage * STAGE_BYTES);
        uint32_t sB = sA + 8192u;

        #pragma unroll
        for (int kq = 0; kq < 2; kq++) {
            const uint32_t kq2 = (uint32_t)(kq << 1);
            uint32_t af[4][4];
            #pragma unroll
            for (int mi = 0; mi < 4; mi++) {
                uint32_t addr = sA + aRowOff[mi] + (((kq2 + aHi) ^ aLow[mi]) << 4);
                ldsm_x4(af[mi][0], af[mi][1], af[mi][2], af[mi][3], addr);
            }
            #pragma unroll
            for (int nj = 0; nj < 4; nj++) {
                uint32_t q0, q1, q2, q3;
                uint32_t addr = sB + bRowOff[nj] + (((kq2 + bHi) ^ bLow[nj]) << 4);
                ldsm_x4(q0, q1, q2, q3, addr);
                #pragma unroll
                for (int mi = 0; mi < 4; mi++) {
                    mma_f16(acc[mi][nj * 2],     af[mi], q0, q1);
                    mma_f16(acc[mi][nj * 2 + 1], af[mi], q2, q3);
                }
            }
        }
        __syncthreads();
        stage = (stage + 1 == NSTAGE) ? 0 : stage + 1;
    }

    // ---- epilogue ----
    size_t rowBase = (((size_t)blockIdx.y) << 7) + wm + g;
    int colBase = (blockIdx.x << 7) + wn + (tg << 1);
    #pragma unroll
    for (int mi = 0; mi < 4; mi++) {
        #pragma unroll
        for (int ni = 0; ni < 8; ni++) {
            size_t r0 = rowBase + (mi << 4);
            int col = colBase + (ni << 3);
            float x0 = acc[mi][ni][0], x1 = acc[mi][ni][1];
            float x2 = acc[mi][ni][2], x3 = acc[mi][ni][3];
            if (act) {
                x0 = 1.f / (1.f + expf(-x0));
                x1 = 1.f / (1.f + expf(-x1));
                x2 = 1.f / (1.f + expf(-x2));
                x3 = 1.f / (1.f + expf(-x3));
            }
            if (Ch) {
                *reinterpret_cast<__half2*>(Ch + r0 * N + col)       = __floats2half2_rn(x0, x1);
                *reinterpret_cast<__half2*>(Ch + (r0 + 8) * N + col) = __floats2half2_rn(x2, x3);
            } else {
                *reinterpret_cast<float2*>(Cf + r0 * N + col)       = make_float2(x0, x1);
                *reinterpret_cast<float2*>(Cf + (r0 + 8) * N + col) = make_float2(x2, x3);
            }
        }
    }
}

// ---------------- 3. wkv scan + gating (fp32 in, fp16 rwkv out) ---------------
#define WKV_U 16
__global__ void wkv_kernel(const float* __restrict__ time_decay,
                           const float* __restrict__ time_first)
{
    int idx = blockIdx.x * blockDim.x + threadIdx.x;   // over BSZ*DDIM
    int b = idx / DDIM;
    int d = idx % DDIM;

    float ew = expf(-expf(time_decay[d]));
    float eu = expf(time_first[d]);

    const float* kp = g_k + (size_t)b * TLEN * DDIM + d;
    const float* vp = g_v + (size_t)b * TLEN * DDIM + d;
    const float* rp = g_r + (size_t)b * TLEN * DDIM + d;
    __half*      op = g_rwkv + (size_t)b * TLEN * DDIM + d;

    float aa = 0.f, bb = 0.f;

    for (int t0 = 0; t0 < TLEN; t0 += WKV_U) {
        float kk[WKV_U], vv[WKV_U], rr[WKV_U];
        #pragma unroll
        for (int i = 0; i < WKV_U; i++) {
            kk[i] = kp[(size_t)(t0 + i) * DDIM];
            vv[i] = vp[(size_t)(t0 + i) * DDIM];
            rr[i] = rp[(size_t)(t0 + i) * DDIM];
        }
        #pragma unroll
        for (int i = 0; i < WKV_U; i++) {
            float ek  = expf(kk[i]);
            float ekv = ek * vv[i];
            float out = (eu * ekv + aa) / (eu * ek + bb);
            op[(size_t)(t0 + i) * DDIM] = __float2half(rr[i] * out);
            aa = ew * aa + ekv;
            bb = ew * bb + ek;
        }
    }
}

// ---------------- launch ------------------------------------------------------
extern "C" void kernel_launch(void* const* d_in, const int* in_sizes, int n_in,
                              void* d_out, int out_size)
{
    const float* x    = (const float*)d_in[0];
    const float* td   = (const float*)d_in[1];
    const float* tf   = (const float*)d_in[2];
    const float* tmk  = (const float*)d_in[3];
    const float* tmv  = (const float*)d_in[4];
    const float* tmr  = (const float*)d_in[5];
    const float* Wk   = (const float*)d_in[6];
    const float* Wv   = (const float*)d_in[7];
    const float* Wr   = (const float*)d_in[8];
    const float* Wo   = (const float*)d_in[9];
    float* out = (float*)d_out;

    __half *p_xk, *p_xv, *p_xr, *p_rwkv, *p_Wk, *p_Wv, *p_Wr, *p_Wo;
    float *p_k, *p_v, *p_r;
    cudaGetSymbolAddress((void**)&p_xk, g_xk);
    cudaGetSymbolAddress((void**)&p_xv, g_xv);
    cudaGetSymbolAddress((void**)&p_xr, g_xr);
    cudaGetSymbolAddress((void**)&p_k,  g_k);
    cudaGetSymbolAddress((void**)&p_v,  g_v);
    cudaGetSymbolAddress((void**)&p_r,  g_r);
    cudaGetSymbolAddress((void**)&p_rwkv, g_rwkv);
    cudaGetSymbolAddress((void**)&p_Wk, g_Wk);
    cudaGetSymbolAddress((void**)&p_Wv, g_Wv);
    cudaGetSymbolAddress((void**)&p_Wr, g_Wr);
    cudaGetSymbolAddress((void**)&p_Wo, g_Wo);

    size_t smem = (size_t)NSTAGE * STAGE_BYTES;
    cudaFuncSetAttribute(gemm_f16, cudaFuncAttributeMaxDynamicSharedMemorySize,
                         (int)smem);

    // 0. convert weights to fp16 (single launch)
    {
        int n4 = 4 * (DDIM * CDIM) / 4;
        round_weights<<<n4 / 256, 256>>>(Wk, Wv, Wr, Wo);
    }

    // 1. mixing (fp16 outputs)
    {
        int n = MTOT * CDIM / 4;
        mix_kernel<<<n / 256, 256>>>(x, tmk, tmv, tmr);
    }

    // 2. projections on tensor cores (fp16 in, fp32 out)
    dim3 grid(DDIM / 128, MTOT / 128);
    gemm_f16<<<grid, 128, smem>>>(p_xk, p_Wk, p_k, nullptr, MTOT, DDIM, CDIM, 0);
    gemm_f16<<<grid, 128, smem>>>(p_xv, p_Wv, p_v, nullptr, MTOT, DDIM, CDIM, 0);
    gemm_f16<<<grid, 128, smem>>>(p_xr, p_Wr, p_r, nullptr, MTOT, DDIM, CDIM, 1);

    // 3. wkv scan (+ gate by sigmoid(r)), fp16 rwkv out
    wkv_kernel<<<(BSZ * DDIM) / 64, 64>>>(td, tf);

    // 4. output projection (fp16 in, fp32 out -> d_out)
    dim3 grid2(CDIM / 128, MTOT / 128);
    gemm_f16<<<grid2, 128, smem>>>(p_rwkv, p_Wo, out, nullptr, MTOT, CDIM, DDIM, 0);
}

// round 11
// speedup vs baseline: 1.3200x; 1.3200x over previous
#include <cuda_runtime.h>
#include <cuda_fp16.h>
#include <math.h>
#include <stdint.h>

#define BSZ   8
#define TLEN  2048
#define CDIM  1024
#define DDIM  1024
#define MTOT  (BSZ * TLEN)   // 16384

// ---------------- scratch (static device globals; no allocs allowed) ----------
__device__ __align__(256) __half g_xk[MTOT * CDIM];
__device__ __align__(256) __half g_xv[MTOT * CDIM];
__device__ __align__(256) __half g_xr[MTOT * CDIM];
__device__ __align__(256) float  g_k [MTOT * DDIM];
__device__ __align__(256) float  g_v [MTOT * DDIM];
__device__ __align__(256) float  g_r [MTOT * DDIM];   // sigmoid(r)
__device__ __align__(256) __half g_rwkv[MTOT * DDIM];
__device__ __align__(256) __half g_Wk[DDIM * CDIM];
__device__ __align__(256) __half g_Wv[DDIM * CDIM];
__device__ __align__(256) __half g_Wr[DDIM * CDIM];
__device__ __align__(256) __half g_Wo[CDIM * DDIM];

// ---------------- helpers ------------------------------------------------------
__device__ __forceinline__ void mma_f16(float c[4], const uint32_t a[4],
                                        uint32_t b0, uint32_t b1) {
    asm volatile(
        "mma.sync.aligned.m16n8k16.row.col.f32.f16.f16.f32 "
        "{%0,%1,%2,%3}, {%4,%5,%6,%7}, {%8,%9}, {%0,%1,%2,%3};"
        : "+f"(c[0]), "+f"(c[1]), "+f"(c[2]), "+f"(c[3])
        : "r"(a[0]), "r"(a[1]), "r"(a[2]), "r"(a[3]), "r"(b0), "r"(b1));
}

__device__ __forceinline__ void cp_async16(uint32_t dst, const void* src) {
    asm volatile("cp.async.cg.shared.global [%0], [%1], 16;" ::"r"(dst), "l"(src));
}

__device__ __forceinline__ void ldsm_x4(uint32_t& r0, uint32_t& r1,
                                        uint32_t& r2, uint32_t& r3, uint32_t addr) {
    asm volatile("ldmatrix.sync.aligned.m8n8.x4.shared.b16 {%0,%1,%2,%3}, [%4];"
                 : "=r"(r0), "=r"(r1), "=r"(r2), "=r"(r3) : "r"(addr));
}

union HalfPack {
    __half2 h[2];
    uint2 u;
};

// ---------------- 0. convert all four weight matrices to fp16 -----------------
__global__ void round_weights(const float* __restrict__ wk, const float* __restrict__ wv,
                              const float* __restrict__ wr, const float* __restrict__ wo)
{
    const int per = (DDIM * CDIM) / 4;        // float4s per weight
    int i = blockIdx.x * blockDim.x + threadIdx.x;
    int sel = i / per;
    int off = i - sel * per;
    const float* s = (sel == 0) ? wk : (sel == 1) ? wv : (sel == 2) ? wr : wo;
    __half* d = (sel == 0) ? g_Wk : (sel == 1) ? g_Wv : (sel == 2) ? g_Wr : g_Wo;
    float4 v = reinterpret_cast<const float4*>(s)[off];
    HalfPack p;
    p.h[0] = __floats2half2_rn(v.x, v.y);
    p.h[1] = __floats2half2_rn(v.z, v.w);
    reinterpret_cast<uint2*>(d)[off] = p.u;
}

// ---------------- 1. time-shift + mixing (fp16 outputs) -----------------------
__global__ void mix_kernel(const float* __restrict__ x,
                           const float* __restrict__ tmk,
                           const float* __restrict__ tmv,
                           const float* __restrict__ tmr)
{
    int idx = blockIdx.x * blockDim.x + threadIdx.x;     // over MTOT * CDIM / 4
    const int c4cnt = CDIM / 4;
    int c4 = idx % c4cnt;
    int m  = idx / c4cnt;
    int t  = m % TLEN;

    float4 xv4 = reinterpret_cast<const float4*>(x)[idx];
    float4 xx4 = (t > 0) ? reinterpret_cast<const float4*>(x)[idx - c4cnt]
                         : make_float4(0.f, 0.f, 0.f, 0.f);
    float4 mk = reinterpret_cast<const float4*>(tmk)[c4];
    float4 mv = reinterpret_cast<const float4*>(tmv)[c4];
    float4 mr = reinterpret_cast<const float4*>(tmr)[c4];

    HalfPack pk, pv, pr;
    pk.h[0] = __floats2half2_rn(xv4.x * mk.x + xx4.x * (1.f - mk.x),
                                xv4.y * mk.y + xx4.y * (1.f - mk.y));
    pk.h[1] = __floats2half2_rn(xv4.z * mk.z + xx4.z * (1.f - mk.z),
                                xv4.w * mk.w + xx4.w * (1.f - mk.w));
    pv.h[0] = __floats2half2_rn(xv4.x * mv.x + xx4.x * (1.f - mv.x),
                                xv4.y * mv.y + xx4.y * (1.f - mv.y));
    pv.h[1] = __floats2half2_rn(xv4.z * mv.z + xx4.z * (1.f - mv.z),
                                xv4.w * mv.w + xx4.w * (1.f - mv.w));
    pr.h[0] = __floats2half2_rn(xv4.x * mr.x + xx4.x * (1.f - mr.x),
                                xv4.y * mr.y + xx4.y * (1.f - mr.y));
    pr.h[1] = __floats2half2_rn(xv4.z * mr.z + xx4.z * (1.f - mr.z),
                                xv4.w * mr.w + xx4.w * (1.f - mr.w));

    reinterpret_cast<uint2*>(g_xk)[idx] = pk.u;
    reinterpret_cast<uint2*>(g_xv)[idx] = pv.u;
    reinterpret_cast<uint2*>(g_xr)[idx] = pr.u;
}

// ---------------- 2. fp16 tensor-core GEMM:  C[M,N] = A[M,K] * B[N,K]^T -------
// 128x128x32 tile, 256 threads / 8 warps (warp tile 64x32), 4-stage cp.async
// pipeline, XOR-swizzled fp16 smem (64B rows) + ldmatrix.x4 + m16n8k16.
#define STAGE_BYTES 16384   // A 128*64B + B 128*64B
#define NSTAGE 4

__global__ __launch_bounds__(256, 2)
void gemm_f16(const __half* __restrict__ A, const __half* __restrict__ B,
              float* __restrict__ Cf, __half* __restrict__ Ch,
              int M, int N, int K, int act)
{
    extern __shared__ char smc[];
    const int tid  = threadIdx.x;
    const int lane = tid & 31;
    const int wid  = tid >> 5;          // 0..7
    const int wm = (wid >> 2) << 6;     // 0 or 64
    const int wn = (wid & 3) << 5;      // 0,32,64,96
    const int g  = lane >> 2;           // 0..7
    const int tg = lane & 3;            // 0..3
    const int hi = lane >> 3;           // 0..3
    const int rr = lane & 7;            // 0..7

    // ---- producer: 2 threads per tile row; each does 2 x 16B chunks ----
    const int prow = tid >> 1;          // 0..127
    const int pc0  = (tid & 1) << 1;    // chunk 0 or 2
    const uint32_t pswz = (uint32_t)((prow >> 1) & 3);

    const __half* Ag = A + ((((size_t)blockIdx.y) << 7) + prow) * K + (pc0 << 3);
    const __half* Bg = B + ((((size_t)blockIdx.x) << 7) + prow) * K + (pc0 << 3);

    uint32_t sbase = (uint32_t)__cvta_generic_to_shared(smc);
    uint32_t dA = sbase + (uint32_t)(prow << 6);     // row * 64B
    uint32_t dB = dA + 8192u;

    // ---- ldmatrix per-lane address precompute ----
    // A x4 tiles: (m,kk),(m+8,kk),(m,kk+8),(m+8,kk+8); hi&1->+8 rows, hi>>1->+8 k
    uint32_t aRowOff[4], aLow[4];
    #pragma unroll
    for (int mi = 0; mi < 4; mi++) {
        int row = wm + (mi << 4) + ((hi & 1) << 3) + rr;
        aRowOff[mi] = (uint32_t)(row << 6);
        aLow[mi] = (uint32_t)((row >> 1) & 3);
    }
    const uint32_t aHi = (uint32_t)(hi >> 1);
    // B x4 tiles: (n0,kk),(n0,kk+8),(n0+8,kk),(n0+8,kk+8); hi>>1->+8 rows, hi&1->+8 k
    uint32_t bRowOff[2], bLow[2];
    #pragma unroll
    for (int nj = 0; nj < 2; nj++) {
        int row = wn + (nj << 4) + ((hi >> 1) << 3) + rr;
        bRowOff[nj] = (uint32_t)(row << 6);
        bLow[nj] = (uint32_t)((row >> 1) & 3);
    }
    const uint32_t bHi = (uint32_t)(hi & 1);

    float acc[4][4][4];
    #pragma unroll
    for (int i = 0; i < 4; i++)
        #pragma unroll
        for (int j = 0; j < 4; j++)
            #pragma unroll
            for (int l = 0; l < 4; l++) acc[i][j][l] = 0.f;

    const int kIters = K >> 5;

#define ISSUEH(IT, S)                                                          \
    {                                                                          \
        uint32_t offS = (uint32_t)((S) * STAGE_BYTES);                         \
        const __half* ap = Ag + (size_t)(IT) * 32;                             \
        const __half* bp = Bg + (size_t)(IT) * 32;                             \
        _Pragma("unroll")                                                      \
        for (int c = 0; c < 2; c++) {                                          \
            uint32_t off = (((uint32_t)(pc0 + c) ^ pswz) << 4);                \
            cp_async16(dA + offS + off, ap + (c << 3));                        \
            cp_async16(dB + offS + off, bp + (c << 3));                        \
        }                                                                      \
        asm volatile("cp.async.commit_group;" ::);                             \
    }

    ISSUEH(0, 0);
    ISSUEH(1, 1);
    ISSUEH(2, 2);

    for (int it = 0; it < kIters; ++it) {
        int rem = kIters - 1 - it;
        if (rem >= 2)      asm volatile("cp.async.wait_group 2;" ::);
        else if (rem == 1) asm volatile("cp.async.wait_group 1;" ::);
        else               asm volatile("cp.async.wait_group 0;" ::);
        __syncthreads();

        if (it + 3 < kIters) ISSUEH(it + 3, (it + 3) & 3);

        uint32_t sA = sbase + (uint32_t)((it & 3) * STAGE_BYTES);
        uint32_t sB = sA + 8192u;

        #pragma unroll
        for (int kq = 0; kq < 2; kq++) {
            const uint32_t kq2 = (uint32_t)(kq << 1);
            uint32_t af[4][4];
            #pragma unroll
            for (int mi = 0; mi < 4; mi++) {
                uint32_t addr = sA + aRowOff[mi] + (((kq2 + aHi) ^ aLow[mi]) << 4);
                ldsm_x4(af[mi][0], af[mi][1], af[mi][2], af[mi][3], addr);
            }
            #pragma unroll
            for (int nj = 0; nj < 2; nj++) {
                uint32_t q0, q1, q2, q3;
                uint32_t addr = sB + bRowOff[nj] + (((kq2 + bHi) ^ bLow[nj]) << 4);
                ldsm_x4(q0, q1, q2, q3, addr);
                #pragma unroll
                for (int mi = 0; mi < 4; mi++) {
                    mma_f16(acc[mi][nj * 2],     af[mi], q0, q1);
                    mma_f16(acc[mi][nj * 2 + 1], af[mi], q2, q3);
                }
            }
        }
    }

    // ---- epilogue ----
    size_t rowBase = (((size_t)blockIdx.y) << 7) + wm + g;
    int colBase = (blockIdx.x << 7) + wn + (tg << 1);
    #pragma unroll
    for (int mi = 0; mi < 4; mi++) {
        #pragma unroll
        for (int ni = 0; ni < 4; ni++) {
            size_t r0 = rowBase + (mi << 4);
            int col = colBase + (ni << 3);
            float x0 = acc[mi][ni][0], x1 = acc[mi][ni][1];
            float x2 = acc[mi][ni][2], x3 = acc[mi][ni][3];
            if (act) {
                x0 = 1.f / (1.f + expf(-x0));
                x1 = 1.f / (1.f + expf(-x1));
                x2 = 1.f / (1.f + expf(-x2));
                x3 = 1.f / (1.f + expf(-x3));
            }
            if (Ch) {
                *reinterpret_cast<__half2*>(Ch + r0 * N + col)       = __floats2half2_rn(x0, x1);
                *reinterpret_cast<__half2*>(Ch + (r0 + 8) * N + col) = __floats2half2_rn(x2, x3);
            } else {
                *reinterpret_cast<float2*>(Cf + r0 * N + col)       = make_float2(x0, x1);
                *reinterpret_cast<float2*>(Cf + (r0 + 8) * N + col) = make_float2(x2, x3);
            }
        }
    }
}

// ---------------- 3. wkv scan + gating (fp32 in, fp16 rwkv out) ---------------
#define WKV_U 16
__global__ void wkv_kernel(const float* __restrict__ time_decay,
                           const float* __restrict__ time_first)
{
    int idx = blockIdx.x * blockDim.x + threadIdx.x;   // over BSZ*DDIM
    int b = idx / DDIM;
    int d = idx % DDIM;

    float ew = expf(-expf(time_decay[d]));
    float eu = expf(time_first[d]);

    const float* kp = g_k + (size_t)b * TLEN * DDIM + d;
    const float* vp = g_v + (size_t)b * TLEN * DDIM + d;
    const float* rp = g_r + (size_t)b * TLEN * DDIM + d;
    __half*      op = g_rwkv + (size_t)b * TLEN * DDIM + d;

    float aa = 0.f, bb = 0.f;

    for (int t0 = 0; t0 < TLEN; t0 += WKV_U) {
        float kk[WKV_U], vv[WKV_U], rr[WKV_U];
        #pragma unroll
        for (int i = 0; i < WKV_U; i++) {
            kk[i] = kp[(size_t)(t0 + i) * DDIM];
            vv[i] = vp[(size_t)(t0 + i) * DDIM];
            rr[i] = rp[(size_t)(t0 + i) * DDIM];
        }
        #pragma unroll
        for (int i = 0; i < WKV_U; i++) {
            float ek  = expf(kk[i]);
            float ekv = ek * vv[i];
            float out = (eu * ekv + aa) / (eu * ek + bb);
            op[(size_t)(t0 + i) * DDIM] = __float2half(rr[i] * out);
            aa = ew * aa + ekv;
            bb = ew * bb + ek;
        }
    }
}

// ---------------- launch ------------------------------------------------------
extern "C" void kernel_launch(void* const* d_in, const int* in_sizes, int n_in,
                              void* d_out, int out_size)
{
    const float* x    = (const float*)d_in[0];
    const float* td   = (const float*)d_in[1];
    const float* tf   = (const float*)d_in[2];
    const float* tmk  = (const float*)d_in[3];
    const float* tmv  = (const float*)d_in[4];
    const float* tmr  = (const float*)d_in[5];
    const float* Wk   = (const float*)d_in[6];
    const float* Wv   = (const float*)d_in[7];
    const float* Wr   = (const float*)d_in[8];
    const float* Wo   = (const float*)d_in[9];
    float* out = (float*)d_out;

    __half *p_xk, *p_xv, *p_xr, *p_rwkv, *p_Wk, *p_Wv, *p_Wr, *p_Wo;
    float *p_k, *p_v, *p_r;
    cudaGetSymbolAddress((void**)&p_xk, g_xk);
    cudaGetSymbolAddress((void**)&p_xv, g_xv);
    cudaGetSymbolAddress((void**)&p_xr, g_xr);
    cudaGetSymbolAddress((void**)&p_k,  g_k);
    cudaGetSymbolAddress((void**)&p_v,  g_v);
    cudaGetSymbolAddress((void**)&p_r,  g_r);
    cudaGetSymbolAddress((void**)&p_rwkv, g_rwkv);
    cudaGetSymbolAddress((void**)&p_Wk, g_Wk);
    cudaGetSymbolAddress((void**)&p_Wv, g_Wv);
    cudaGetSymbolAddress((void**)&p_Wr, g_Wr);
    cudaGetSymbolAddress((void**)&p_Wo, g_Wo);

    size_t smem = (size_t)NSTAGE * STAGE_BYTES;   // 64 KB
    cudaFuncSetAttribute(gemm_f16, cudaFuncAttributeMaxDynamicSharedMemorySize,
                         (int)smem);

    // 0. convert weights to fp16 (single launch)
    {
        int n4 = 4 * (DDIM * CDIM) / 4;
        round_weights<<<n4 / 256, 256>>>(Wk, Wv, Wr, Wo);
    }

    // 1. mixing (fp16 outputs)
    {
        int n = MTOT * CDIM / 4;
        mix_kernel<<<n / 256, 256>>>(x, tmk, tmv, tmr);
    }

    // 2. projections on tensor cores (fp16 in, fp32 out)
    dim3 grid(DDIM / 128, MTOT / 128);
    gemm_f16<<<grid, 256, smem>>>(p_xk, p_Wk, p_k, nullptr, MTOT, DDIM, CDIM, 0);
    gemm_f16<<<grid, 256, smem>>>(p_xv, p_Wv, p_v, nullptr, MTOT, DDIM, CDIM, 0);
    gemm_f16<<<grid, 256, smem>>>(p_xr, p_Wr, p_r, nullptr, MTOT, DDIM, CDIM, 1);

    // 3. wkv scan (+ gate by sigmoid(r)), fp16 rwkv out
    wkv_kernel<<<(BSZ * DDIM) / 64, 64>>>(td, tf);

    // 4. output projection (fp16 in, fp32 out -> d_out)
    dim3 grid2(CDIM / 128, MTOT / 128);
    gemm_f16<<<grid2, 256, smem>>>(p_rwkv, p_Wo, out, nullptr, MTOT, CDIM, DDIM, 0);
}

// round 13
// speedup vs baseline: 1.4615x; 1.1072x over previous
#include <cuda_runtime.h>
#include <cuda_fp16.h>
#include <math.h>
#include <stdint.h>

#define BSZ   8
#define TLEN  2048
#define CDIM  1024
#define DDIM  1024
#define MTOT  (BSZ * TLEN)   // 16384

// ---------------- scratch (static device globals; no allocs allowed) ----------
__device__ __align__(256) __half g_xk[MTOT * CDIM];
__device__ __align__(256) __half g_xv[MTOT * CDIM];
__device__ __align__(256) __half g_xr[MTOT * CDIM];
__device__ __align__(256) float  g_k [MTOT * DDIM];
__device__ __align__(256) float  g_v [MTOT * DDIM];
__device__ __align__(256) float  g_r [MTOT * DDIM];   // sigmoid(r)
__device__ __align__(256) __half g_rwkv[MTOT * DDIM];
__device__ __align__(256) __half g_Wk[DDIM * CDIM];
__device__ __align__(256) __half g_Wv[DDIM * CDIM];
__device__ __align__(256) __half g_Wr[DDIM * CDIM];
__device__ __align__(256) __half g_Wo[CDIM * DDIM];

// ---------------- helpers ------------------------------------------------------
__device__ __forceinline__ void mma_f16(float c[4], const uint32_t a[4],
                                        uint32_t b0, uint32_t b1) {
    asm volatile(
        "mma.sync.aligned.m16n8k16.row.col.f32.f16.f16.f32 "
        "{%0,%1,%2,%3}, {%4,%5,%6,%7}, {%8,%9}, {%0,%1,%2,%3};"
        : "+f"(c[0]), "+f"(c[1]), "+f"(c[2]), "+f"(c[3])
        : "r"(a[0]), "r"(a[1]), "r"(a[2]), "r"(a[3]), "r"(b0), "r"(b1));
}

__device__ __forceinline__ void cp_async16(uint32_t dst, const void* src) {
    asm volatile("cp.async.cg.shared.global [%0], [%1], 16;" ::"r"(dst), "l"(src));
}

__device__ __forceinline__ void ldsm_x4(uint32_t& r0, uint32_t& r1,
                                        uint32_t& r2, uint32_t& r3, uint32_t addr) {
    asm volatile("ldmatrix.sync.aligned.m8n8.x4.shared.b16 {%0,%1,%2,%3}, [%4];"
                 : "=r"(r0), "=r"(r1), "=r"(r2), "=r"(r3) : "r"(addr));
}

union HalfPack {
    __half2 h[2];
    uint2 u;
};

// ---------------- 0. convert all four weight matrices to fp16 -----------------
__global__ void round_weights(const float* __restrict__ wk, const float* __restrict__ wv,
                              const float* __restrict__ wr, const float* __restrict__ wo)
{
    const int per = (DDIM * CDIM) / 4;
    int i = blockIdx.x * blockDim.x + threadIdx.x;
    int sel = i / per;
    int off = i - sel * per;
    const float* s = (sel == 0) ? wk : (sel == 1) ? wv : (sel == 2) ? wr : wo;
    __half* d = (sel == 0) ? g_Wk : (sel == 1) ? g_Wv : (sel == 2) ? g_Wr : g_Wo;
    float4 v = reinterpret_cast<const float4*>(s)[off];
    HalfPack p;
    p.h[0] = __floats2half2_rn(v.x, v.y);
    p.h[1] = __floats2half2_rn(v.z, v.w);
    reinterpret_cast<uint2*>(d)[off] = p.u;
}

// ---------------- 1. time-shift + mixing (fp16 outputs) -----------------------
__global__ void mix_kernel(const float* __restrict__ x,
                           const float* __restrict__ tmk,
                           const float* __restrict__ tmv,
                           const float* __restrict__ tmr)
{
    int idx = blockIdx.x * blockDim.x + threadIdx.x;
    const int c4cnt = CDIM / 4;
    int c4 = idx % c4cnt;
    int m  = idx / c4cnt;
    int t  = m % TLEN;

    float4 xv4 = reinterpret_cast<const float4*>(x)[idx];
    float4 xx4 = (t > 0) ? reinterpret_cast<const float4*>(x)[idx - c4cnt]
                         : make_float4(0.f, 0.f, 0.f, 0.f);
    float4 mk = reinterpret_cast<const float4*>(tmk)[c4];
    float4 mv = reinterpret_cast<const float4*>(tmv)[c4];
    float4 mr = reinterpret_cast<const float4*>(tmr)[c4];

    HalfPack pk, pv, pr;
    pk.h[0] = __floats2half2_rn(xv4.x * mk.x + xx4.x * (1.f - mk.x),
                                xv4.y * mk.y + xx4.y * (1.f - mk.y));
    pk.h[1] = __floats2half2_rn(xv4.z * mk.z + xx4.z * (1.f - mk.z),
                                xv4.w * mk.w + xx4.w * (1.f - mk.w));
    pv.h[0] = __floats2half2_rn(xv4.x * mv.x + xx4.x * (1.f - mv.x),
                                xv4.y * mv.y + xx4.y * (1.f - mv.y));
    pv.h[1] = __floats2half2_rn(xv4.z * mv.z + xx4.z * (1.f - mv.z),
                                xv4.w * mv.w + xx4.w * (1.f - mv.w));
    pr.h[0] = __floats2half2_rn(xv4.x * mr.x + xx4.x * (1.f - mr.x),
                                xv4.y * mr.y + xx4.y * (1.f - mr.y));
    pr.h[1] = __floats2half2_rn(xv4.z * mr.z + xx4.z * (1.f - mr.z),
                                xv4.w * mr.w + xx4.w * (1.f - mr.w));

    reinterpret_cast<uint2*>(g_xk)[idx] = pk.u;
    reinterpret_cast<uint2*>(g_xv)[idx] = pv.u;
    reinterpret_cast<uint2*>(g_xr)[idx] = pr.u;
}

// ---------------- 2. fp16 tensor-core GEMM:  C[M,N] = A[M,K] * B[N,K]^T -------
// 128x128x32 tile, 512 threads / 16 warps (warp tile 32x32), 4-stage cp.async
// pipeline, XOR-swizzled fp16 smem (64B rows) + ldmatrix.x4 + m16n8k16.
#define STAGE_BYTES 16384   // A 128*64B + B 128*64B
#define NSTAGE 4

__device__ __forceinline__ void gemm_f16_core(
    const __half* __restrict__ A, const __half* __restrict__ B,
    float* __restrict__ Cf, __half* __restrict__ Ch,
    int N, int act, int bx, int by, char* smc)
{
    const int tid  = threadIdx.x;
    const int lane = tid & 31;
    const int wid  = tid >> 5;          // 0..15
    const int wm = (wid >> 2) << 5;     // 0,32,64,96
    const int wn = (wid & 3) << 5;      // 0,32,64,96
    const int g  = lane >> 2;           // 0..7
    const int tg = lane & 3;            // 0..3
    const int hi = lane >> 3;           // 0..3
    const int rr = lane & 7;            // 0..7

    const int K = 1024;

    // ---- producer: 4 threads per tile row; each does 1 x 16B chunk ----
    const int prow = tid >> 2;          // 0..127
    const int pc   = tid & 3;           // chunk 0..3
    const uint32_t psw = ((uint32_t)(pc) ^ (uint32_t)((prow >> 1) & 3)) << 4;

    const __half* Ag = A + ((((size_t)by) << 7) + prow) * K + (pc << 3);
    const __half* Bg = B + ((((size_t)bx) << 7) + prow) * K + (pc << 3);

    uint32_t sbase = (uint32_t)__cvta_generic_to_shared(smc);
    uint32_t dA = sbase + (uint32_t)(prow << 6) + psw;   // row*64B + swz chunk
    uint32_t dB = dA + 8192u;

    // ---- ldmatrix per-lane address precompute ----
    // A x4 tiles: (m,kk),(m+8,kk),(m,kk+8),(m+8,kk+8); hi&1->+8 rows, hi>>1->+8 k
    // +16-row step preserves (row>>1)&3, so one base + 1024B offset covers mi=1.
    uint32_t aRow0, aLow, bRow0, bLow;
    {
        int row = wm + ((hi & 1) << 3) + rr;
        aRow0 = (uint32_t)(row << 6);
        aLow  = (uint32_t)((row >> 1) & 3);
        int rowb = wn + ((hi >> 1) << 3) + rr;
        bRow0 = (uint32_t)(rowb << 6);
        bLow  = (uint32_t)((rowb >> 1) & 3);
    }
    const uint32_t aHi = (uint32_t)(hi >> 1);
    const uint32_t bHi = (uint32_t)(hi & 1);

    float acc[2][4][4];
    #pragma unroll
    for (int i = 0; i < 2; i++)
        #pragma unroll
        for (int j = 0; j < 4; j++)
            #pragma unroll
            for (int l = 0; l < 4; l++) acc[i][j][l] = 0.f;

    const int kIters = K >> 5;          // 32

#define ISSUE1(IT, S)                                                          \
    {                                                                          \
        uint32_t offS = (uint32_t)((S) * STAGE_BYTES);                         \
        cp_async16(dA + offS, Ag + (size_t)(IT) * 32);                         \
        cp_async16(dB + offS, Bg + (size_t)(IT) * 32);                         \
        asm volatile("cp.async.commit_group;" ::);                             \
    }

    ISSUE1(0, 0);
    ISSUE1(1, 1);
    ISSUE1(2, 2);

    for (int it = 0; it < kIters; ++it) {
        int rem = kIters - 1 - it;
        if (rem >= 2)      asm volatile("cp.async.wait_group 2;" ::);
        else if (rem == 1) asm volatile("cp.async.wait_group 1;" ::);
        else               asm volatile("cp.async.wait_group 0;" ::);
        __syncthreads();

        if (it + 3 < kIters) ISSUE1(it + 3, (it + 3) & 3);

        uint32_t sA = sbase + (uint32_t)((it & 3) * STAGE_BYTES);
        uint32_t sB = sA + 8192u;

        #pragma unroll
        for (int kq = 0; kq < 2; kq++) {
            const uint32_t kq2 = (uint32_t)(kq << 1);
            uint32_t af[2][4];
            #pragma unroll
            for (int mi = 0; mi < 2; mi++) {
                uint32_t addr = sA + aRow0 + (uint32_t)(mi << 10) +
                                (((kq2 + aHi) ^ aLow) << 4);
                ldsm_x4(af[mi][0], af[mi][1], af[mi][2], af[mi][3], addr);
            }
            #pragma unroll
            for (int nj = 0; nj < 2; nj++) {
                uint32_t q0, q1, q2, q3;
                uint32_t addr = sB + bRow0 + (uint32_t)(nj << 10) +
                                (((kq2 + bHi) ^ bLow) << 4);
                ldsm_x4(q0, q1, q2, q3, addr);
                #pragma unroll
                for (int mi = 0; mi < 2; mi++) {
                    mma_f16(acc[mi][nj * 2],     af[mi], q0, q1);
                    mma_f16(acc[mi][nj * 2 + 1], af[mi], q2, q3);
                }
            }
        }
    }

    // ---- epilogue ----
    size_t rowBase = (((size_t)by) << 7) + wm + g;
    int colBase = (bx << 7) + wn + (tg << 1);
    #pragma unroll
    for (int mi = 0; mi < 2; mi++) {
        #pragma unroll
        for (int ni = 0; ni < 4; ni++) {
            size_t r0 = rowBase + (mi << 4);
            int col = colBase + (ni << 3);
            float x0 = acc[mi][ni][0], x1 = acc[mi][ni][1];
            float x2 = acc[mi][ni][2], x3 = acc[mi][ni][3];
            if (act) {
                x0 = 1.f / (1.f + expf(-x0));
                x1 = 1.f / (1.f + expf(-x1));
                x2 = 1.f / (1.f + expf(-x2));
                x3 = 1.f / (1.f + expf(-x3));
            }
            if (Ch) {
                *reinterpret_cast<__half2*>(Ch + r0 * N + col)       = __floats2half2_rn(x0, x1);
                *reinterpret_cast<__half2*>(Ch + (r0 + 8) * N + col) = __floats2half2_rn(x2, x3);
            } else {
                *reinterpret_cast<float2*>(Cf + r0 * N + col)       = make_float2(x0, x1);
                *reinterpret_cast<float2*>(Cf + (r0 + 8) * N + col) = make_float2(x2, x3);
            }
        }
    }
}

// merged K/V/R projection GEMMs (z selects operand set)
__global__ __launch_bounds__(512, 2)
void gemm_proj(int dummy)
{
    extern __shared__ char smc[];
    const int z = blockIdx.z;
    const __half* A = (z == 0) ? g_xk : (z == 1) ? g_xv : g_xr;
    const __half* B = (z == 0) ? g_Wk : (z == 1) ? g_Wv : g_Wr;
    float* C        = (z == 0) ? g_k  : (z == 1) ? g_v  : g_r;
    gemm_f16_core(A, B, C, nullptr, DDIM, (z == 2) ? 1 : 0,
                  blockIdx.x, blockIdx.y, smc);
}

// output projection GEMM
__global__ __launch_bounds__(512, 2)
void gemm_out(float* __restrict__ C)
{
    extern __shared__ char smc[];
    gemm_f16_core(g_rwkv, g_Wo, C, nullptr, CDIM, 0, blockIdx.x, blockIdx.y, smc);
}

// ---------------- 3. wkv scan + gating (fp32 in, fp16 rwkv out) ---------------
#define WKV_U 16
__global__ void wkv_kernel(const float* __restrict__ time_decay,
                           const float* __restrict__ time_first)
{
    int idx = blockIdx.x * blockDim.x + threadIdx.x;   // over BSZ*DDIM
    int b = idx / DDIM;
    int d = idx % DDIM;

    float ew = expf(-expf(time_decay[d]));
    float eu = expf(time_first[d]);

    const float* kp = g_k + (size_t)b * TLEN * DDIM + d;
    const float* vp = g_v + (size_t)b * TLEN * DDIM + d;
    const float* rp = g_r + (size_t)b * TLEN * DDIM + d;
    __half*      op = g_rwkv + (size_t)b * TLEN * DDIM + d;

    float aa = 0.f, bb = 0.f;

    for (int t0 = 0; t0 < TLEN; t0 += WKV_U) {
        float kk[WKV_U], vv[WKV_U], rr[WKV_U];
        #pragma unroll
        for (int i = 0; i < WKV_U; i++) {
            kk[i] = kp[(size_t)(t0 + i) * DDIM];
            vv[i] = vp[(size_t)(t0 + i) * DDIM];
            rr[i] = rp[(size_t)(t0 + i) * DDIM];
        }
        #pragma unroll
        for (int i = 0; i < WKV_U; i++) {
            float ek  = expf(kk[i]);
            float ekv = ek * vv[i];
            float out = (eu * ekv + aa) / (eu * ek + bb);
            op[(size_t)(t0 + i) * DDIM] = __float2half(rr[i] * out);
            aa = ew * aa + ekv;
            bb = ew * bb + ek;
        }
    }
}

// ---------------- launch ------------------------------------------------------
extern "C" void kernel_launch(void* const* d_in, const int* in_sizes, int n_in,
                              void* d_out, int out_size)
{
    const float* x    = (const float*)d_in[0];
    const float* td   = (const float*)d_in[1];
    const float* tf   = (const float*)d_in[2];
    const float* tmk  = (const float*)d_in[3];
    const float* tmv  = (const float*)d_in[4];
    const float* tmr  = (const float*)d_in[5];
    const float* Wk   = (const float*)d_in[6];
    const float* Wv   = (const float*)d_in[7];
    const float* Wr   = (const float*)d_in[8];
    const float* Wo   = (const float*)d_in[9];
    float* out = (float*)d_out;

    size_t smem = (size_t)NSTAGE * STAGE_BYTES;   // 64 KB
    cudaFuncSetAttribute(gemm_proj, cudaFuncAttributeMaxDynamicSharedMemorySize,
                         (int)smem);
    cudaFuncSetAttribute(gemm_out, cudaFuncAttributeMaxDynamicSharedMemorySize,
                         (int)smem);

    // 0. convert weights to fp16 (single launch)
    {
        int n4 = 4 * (DDIM * CDIM) / 4;
        round_weights<<<n4 / 256, 256>>>(Wk, Wv, Wr, Wo);
    }

    // 1. mixing (fp16 outputs)
    {
        int n = MTOT * CDIM / 4;
        mix_kernel<<<n / 256, 256>>>(x, tmk, tmv, tmr);
    }

    // 2. K/V/R projections (merged launch)
    {
        dim3 grid(DDIM / 128, MTOT / 128, 3);
        gemm_proj<<<grid, 512, smem>>>(0);
    }

    // 3. wkv scan (+ gate by sigmoid(r)), fp16 rwkv out
    wkv_kernel<<<(BSZ * DDIM) / 64, 64>>>(td, tf);

    // 4. output projection (fp16 in, fp32 out -> d_out)
    {
        dim3 grid(CDIM / 128, MTOT / 128, 1);
        gemm_out<<<grid, 512, smem>>>(out);
    }
}

// round 14
// speedup vs baseline: 1.8174x; 1.2435x over previous
#include <cuda_runtime.h>
#include <cuda_fp16.h>
#include <math.h>
#include <stdint.h>

#define BSZ   8
#define TLEN  2048
#define CDIM  1024
#define DDIM  1024
#define MTOT  (BSZ * TLEN)   // 16384

#define SSEG  32
#define LSEG  (TLEN / SSEG)  // 64

// ---------------- scratch (static device globals; no allocs allowed) ----------
__device__ __align__(256) __half g_xk[MTOT * CDIM];
__device__ __align__(256) __half g_xv[MTOT * CDIM];
__device__ __align__(256) __half g_xr[MTOT * CDIM];
__device__ __align__(256) float  g_k [MTOT * DDIM];
__device__ __align__(256) float  g_v [MTOT * DDIM];
__device__ __align__(256) float  g_r [MTOT * DDIM];   // sigmoid(r)
__device__ __align__(256) __half g_rwkv[MTOT * DDIM];
__device__ __align__(256) __half g_Wk[DDIM * CDIM];
__device__ __align__(256) __half g_Wv[DDIM * CDIM];
__device__ __align__(256) __half g_Wr[DDIM * CDIM];
__device__ __align__(256) __half g_Wo[CDIM * DDIM];
__device__ __align__(256) float  g_sA[BSZ * SSEG * DDIM];
__device__ __align__(256) float  g_sB[BSZ * SSEG * DDIM];

// ---------------- helpers ------------------------------------------------------
__device__ __forceinline__ void mma_f16(float c[4], const uint32_t a[4],
                                        uint32_t b0, uint32_t b1) {
    asm volatile(
        "mma.sync.aligned.m16n8k16.row.col.f32.f16.f16.f32 "
        "{%0,%1,%2,%3}, {%4,%5,%6,%7}, {%8,%9}, {%0,%1,%2,%3};"
        : "+f"(c[0]), "+f"(c[1]), "+f"(c[2]), "+f"(c[3])
        : "r"(a[0]), "r"(a[1]), "r"(a[2]), "r"(a[3]), "r"(b0), "r"(b1));
}

__device__ __forceinline__ void cp_async16(uint32_t dst, const void* src) {
    asm volatile("cp.async.cg.shared.global [%0], [%1], 16;" ::"r"(dst), "l"(src));
}

__device__ __forceinline__ void ldsm_x4(uint32_t& r0, uint32_t& r1,
                                        uint32_t& r2, uint32_t& r3, uint32_t addr) {
    asm volatile("ldmatrix.sync.aligned.m8n8.x4.shared.b16 {%0,%1,%2,%3}, [%4];"
                 : "=r"(r0), "=r"(r1), "=r"(r2), "=r"(r3) : "r"(addr));
}

union HalfPack {
    __half2 h[2];
    uint2 u;
};

// ---------------- 0. convert all four weight matrices to fp16 -----------------
__global__ void round_weights(const float* __restrict__ wk, const float* __restrict__ wv,
                              const float* __restrict__ wr, const float* __restrict__ wo)
{
    const int per = (DDIM * CDIM) / 4;
    int i = blockIdx.x * blockDim.x + threadIdx.x;
    int sel = i / per;
    int off = i - sel * per;
    const float* s = (sel == 0) ? wk : (sel == 1) ? wv : (sel == 2) ? wr : wo;
    __half* d = (sel == 0) ? g_Wk : (sel == 1) ? g_Wv : (sel == 2) ? g_Wr : g_Wo;
    float4 v = reinterpret_cast<const float4*>(s)[off];
    HalfPack p;
    p.h[0] = __floats2half2_rn(v.x, v.y);
    p.h[1] = __floats2half2_rn(v.z, v.w);
    reinterpret_cast<uint2*>(d)[off] = p.u;
}

// ---------------- 1. time-shift + mixing (fp16 outputs) -----------------------
__global__ void mix_kernel(const float* __restrict__ x,
                           const float* __restrict__ tmk,
                           const float* __restrict__ tmv,
                           const float* __restrict__ tmr)
{
    int idx = blockIdx.x * blockDim.x + threadIdx.x;
    const int c4cnt = CDIM / 4;
    int c4 = idx % c4cnt;
    int m  = idx / c4cnt;
    int t  = m % TLEN;

    float4 xv4 = reinterpret_cast<const float4*>(x)[idx];
    float4 xx4 = (t > 0) ? reinterpret_cast<const float4*>(x)[idx - c4cnt]
                         : make_float4(0.f, 0.f, 0.f, 0.f);
    float4 mk = reinterpret_cast<const float4*>(tmk)[c4];
    float4 mv = reinterpret_cast<const float4*>(tmv)[c4];
    float4 mr = reinterpret_cast<const float4*>(tmr)[c4];

    HalfPack pk, pv, pr;
    pk.h[0] = __floats2half2_rn(xv4.x * mk.x + xx4.x * (1.f - mk.x),
                                xv4.y * mk.y + xx4.y * (1.f - mk.y));
    pk.h[1] = __floats2half2_rn(xv4.z * mk.z + xx4.z * (1.f - mk.z),
                                xv4.w * mk.w + xx4.w * (1.f - mk.w));
    pv.h[0] = __floats2half2_rn(xv4.x * mv.x + xx4.x * (1.f - mv.x),
                                xv4.y * mv.y + xx4.y * (1.f - mv.y));
    pv.h[1] = __floats2half2_rn(xv4.z * mv.z + xx4.z * (1.f - mv.z),
                                xv4.w * mv.w + xx4.w * (1.f - mv.w));
    pr.h[0] = __floats2half2_rn(xv4.x * mr.x + xx4.x * (1.f - mr.x),
                                xv4.y * mr.y + xx4.y * (1.f - mr.y));
    pr.h[1] = __floats2half2_rn(xv4.z * mr.z + xx4.z * (1.f - mr.z),
                                xv4.w * mr.w + xx4.w * (1.f - mr.w));

    reinterpret_cast<uint2*>(g_xk)[idx] = pk.u;
    reinterpret_cast<uint2*>(g_xv)[idx] = pv.u;
    reinterpret_cast<uint2*>(g_xr)[idx] = pr.u;
}

// ---------------- 2. fp16 tensor-core GEMM (proven R13 core) ------------------
#define STAGE_BYTES 16384
#define NSTAGE 4

__device__ __forceinline__ void gemm_f16_core(
    const __half* __restrict__ A, const __half* __restrict__ B,
    float* __restrict__ Cf, __half* __restrict__ Ch,
    int N, int act, int bx, int by, char* smc)
{
    const int tid  = threadIdx.x;
    const int lane = tid & 31;
    const int wid  = tid >> 5;          // 0..15
    const int wm = (wid >> 2) << 5;
    const int wn = (wid & 3) << 5;
    const int g  = lane >> 2;
    const int tg = lane & 3;
    const int hi = lane >> 3;
    const int rr = lane & 7;

    const int K = 1024;

    const int prow = tid >> 2;
    const int pc   = tid & 3;
    const uint32_t psw = ((uint32_t)(pc) ^ (uint32_t)((prow >> 1) & 3)) << 4;

    const __half* Ag = A + ((((size_t)by) << 7) + prow) * K + (pc << 3);
    const __half* Bg = B + ((((size_t)bx) << 7) + prow) * K + (pc << 3);

    uint32_t sbase = (uint32_t)__cvta_generic_to_shared(smc);
    uint32_t dA = sbase + (uint32_t)(prow << 6) + psw;
    uint32_t dB = dA + 8192u;

    uint32_t aRow0, aLow, bRow0, bLow;
    {
        int row = wm + ((hi & 1) << 3) + rr;
        aRow0 = (uint32_t)(row << 6);
        aLow  = (uint32_t)((row >> 1) & 3);
        int rowb = wn + ((hi >> 1) << 3) + rr;
        bRow0 = (uint32_t)(rowb << 6);
        bLow  = (uint32_t)((rowb >> 1) & 3);
    }
    const uint32_t aHi = (uint32_t)(hi >> 1);
    const uint32_t bHi = (uint32_t)(hi & 1);

    float acc[2][4][4];
    #pragma unroll
    for (int i = 0; i < 2; i++)
        #pragma unroll
        for (int j = 0; j < 4; j++)
            #pragma unroll
            for (int l = 0; l < 4; l++) acc[i][j][l] = 0.f;

    const int kIters = K >> 5;

#define ISSUE1(IT, S)                                                          \
    {                                                                          \
        uint32_t offS = (uint32_t)((S) * STAGE_BYTES);                         \
        cp_async16(dA + offS, Ag + (size_t)(IT) * 32);                         \
        cp_async16(dB + offS, Bg + (size_t)(IT) * 32);                         \
        asm volatile("cp.async.commit_group;" ::);                             \
    }

    ISSUE1(0, 0);
    ISSUE1(1, 1);
    ISSUE1(2, 2);

    for (int it = 0; it < kIters; ++it) {
        int rem = kIters - 1 - it;
        if (rem >= 2)      asm volatile("cp.async.wait_group 2;" ::);
        else if (rem == 1) asm volatile("cp.async.wait_group 1;" ::);
        else               asm volatile("cp.async.wait_group 0;" ::);
        __syncthreads();

        if (it + 3 < kIters) ISSUE1(it + 3, (it + 3) & 3);

        uint32_t sA = sbase + (uint32_t)((it & 3) * STAGE_BYTES);
        uint32_t sB = sA + 8192u;

        #pragma unroll
        for (int kq = 0; kq < 2; kq++) {
            const uint32_t kq2 = (uint32_t)(kq << 1);
            uint32_t af[2][4];
            #pragma unroll
            for (int mi = 0; mi < 2; mi++) {
                uint32_t addr = sA + aRow0 + (uint32_t)(mi << 10) +
                                (((kq2 + aHi) ^ aLow) << 4);
                ldsm_x4(af[mi][0], af[mi][1], af[mi][2], af[mi][3], addr);
            }
            #pragma unroll
            for (int nj = 0; nj < 2; nj++) {
                uint32_t q0, q1, q2, q3;
                uint32_t addr = sB + bRow0 + (uint32_t)(nj << 10) +
                                (((kq2 + bHi) ^ bLow) << 4);
                ldsm_x4(q0, q1, q2, q3, addr);
                #pragma unroll
                for (int mi = 0; mi < 2; mi++) {
                    mma_f16(acc[mi][nj * 2],     af[mi], q0, q1);
                    mma_f16(acc[mi][nj * 2 + 1], af[mi], q2, q3);
                }
            }
        }
    }

    size_t rowBase = (((size_t)by) << 7) + wm + g;
    int colBase = (bx << 7) + wn + (tg << 1);
    #pragma unroll
    for (int mi = 0; mi < 2; mi++) {
        #pragma unroll
        for (int ni = 0; ni < 4; ni++) {
            size_t r0 = rowBase + (mi << 4);
            int col = colBase + (ni << 3);
            float x0 = acc[mi][ni][0], x1 = acc[mi][ni][1];
            float x2 = acc[mi][ni][2], x3 = acc[mi][ni][3];
            if (act) {
                x0 = 1.f / (1.f + expf(-x0));
                x1 = 1.f / (1.f + expf(-x1));
                x2 = 1.f / (1.f + expf(-x2));
                x3 = 1.f / (1.f + expf(-x3));
            }
            if (Ch) {
                *reinterpret_cast<__half2*>(Ch + r0 * N + col)       = __floats2half2_rn(x0, x1);
                *reinterpret_cast<__half2*>(Ch + (r0 + 8) * N + col) = __floats2half2_rn(x2, x3);
            } else {
                *reinterpret_cast<float2*>(Cf + r0 * N + col)       = make_float2(x0, x1);
                *reinterpret_cast<float2*>(Cf + (r0 + 8) * N + col) = make_float2(x2, x3);
            }
        }
    }
}

__global__ __launch_bounds__(512, 2)
void gemm_proj(int dummy)
{
    extern __shared__ char smc[];
    const int z = blockIdx.z;
    const __half* A = (z == 0) ? g_xk : (z == 1) ? g_xv : g_xr;
    const __half* B = (z == 0) ? g_Wk : (z == 1) ? g_Wv : g_Wr;
    float* C        = (z == 0) ? g_k  : (z == 1) ? g_v  : g_r;
    gemm_f16_core(A, B, C, nullptr, DDIM, (z == 2) ? 1 : 0,
                  blockIdx.x, blockIdx.y, smc);
}

__global__ __launch_bounds__(512, 2)
void gemm_out(float* __restrict__ C)
{
    extern __shared__ char smc[];
    gemm_f16_core(g_rwkv, g_Wo, C, nullptr, CDIM, 0, blockIdx.x, blockIdx.y, smc);
}

// ---------------- 3. wkv: segmented parallel scan -----------------------------
// pass1: per-(b,s,d) segment summaries A,B  (grid: DDIM/256 x SSEG x BSZ)
#define P1U 8
__global__ __launch_bounds__(256)
void wkv_pass1(const float* __restrict__ time_decay)
{
    int d = blockIdx.x * 256 + threadIdx.x;
    int s = blockIdx.y;
    int b = blockIdx.z;

    float ew = expf(-expf(time_decay[d]));
    const size_t base = ((size_t)b * TLEN + (size_t)s * LSEG) * DDIM + d;
    const float* kp = g_k + base;
    const float* vp = g_v + base;

    float a = 0.f, bb = 0.f;
    for (int t0 = 0; t0 < LSEG; t0 += P1U) {
        float kk[P1U], vv[P1U];
        #pragma unroll
        for (int i = 0; i < P1U; i++) {
            kk[i] = kp[(size_t)(t0 + i) * DDIM];
            vv[i] = vp[(size_t)(t0 + i) * DDIM];
        }
        #pragma unroll
        for (int i = 0; i < P1U; i++) {
            float ek  = expf(kk[i]);
            float ekv = ek * vv[i];
            a  = ew * a  + ekv;
            bb = ew * bb + ek;
        }
    }
    size_t so = ((size_t)b * SSEG + s) * DDIM + d;
    g_sA[so] = a;
    g_sB[so] = bb;
}

// scan: per-(b,d) exclusive scan over the SSEG summaries (in place)
__global__ __launch_bounds__(256)
void wkv_scan(const float* __restrict__ time_decay)
{
    int idx = blockIdx.x * 256 + threadIdx.x;   // over BSZ*DDIM
    int b = idx / DDIM;
    int d = idx % DDIM;

    float ewL = expf(-expf(time_decay[d]) * (float)LSEG);   // ew^LSEG exactly
    float a = 0.f, bb = 0.f;
    #pragma unroll 4
    for (int s = 0; s < SSEG; s++) {
        size_t o = ((size_t)b * SSEG + s) * DDIM + d;
        float A = g_sA[o], B = g_sB[o];
        g_sA[o] = a;
        g_sB[o] = bb;
        a  = ewL * a  + A;
        bb = ewL * bb + B;
    }
}

// pass2: per-(b,s,d) outputs from carry  (grid: DDIM/256 x SSEG x BSZ)
#define P2U 8
__global__ __launch_bounds__(256)
void wkv_pass2(const float* __restrict__ time_decay,
               const float* __restrict__ time_first)
{
    int d = blockIdx.x * 256 + threadIdx.x;
    int s = blockIdx.y;
    int b = blockIdx.z;

    float ew = expf(-expf(time_decay[d]));
    float eu = expf(time_first[d]);

    size_t so = ((size_t)b * SSEG + s) * DDIM + d;
    float a = g_sA[so], bb = g_sB[so];

    const size_t base = ((size_t)b * TLEN + (size_t)s * LSEG) * DDIM + d;
    const float* kp = g_k + base;
    const float* vp = g_v + base;
    const float* rp = g_r + base;
    __half*      op = g_rwkv + base;

    for (int t0 = 0; t0 < LSEG; t0 += P2U) {
        float kk[P2U], vv[P2U], rr[P2U];
        #pragma unroll
        for (int i = 0; i < P2U; i++) {
            kk[i] = kp[(size_t)(t0 + i) * DDIM];
            vv[i] = vp[(size_t)(t0 + i) * DDIM];
            rr[i] = rp[(size_t)(t0 + i) * DDIM];
        }
        #pragma unroll
        for (int i = 0; i < P2U; i++) {
            float ek  = expf(kk[i]);
            float ekv = ek * vv[i];
            float out = (eu * ekv + a) / (eu * ek + bb);
            op[(size_t)(t0 + i) * DDIM] = __float2half(rr[i] * out);
            a  = ew * a  + ekv;
            bb = ew * bb + ek;
        }
    }
}

// ---------------- launch ------------------------------------------------------
extern "C" void kernel_launch(void* const* d_in, const int* in_sizes, int n_in,
                              void* d_out, int out_size)
{
    const float* x    = (const float*)d_in[0];
    const float* td   = (const float*)d_in[1];
    const float* tf   = (const float*)d_in[2];
    const float* tmk  = (const float*)d_in[3];
    const float* tmv  = (const float*)d_in[4];
    const float* tmr  = (const float*)d_in[5];
    const float* Wk   = (const float*)d_in[6];
    const float* Wv   = (const float*)d_in[7];
    const float* Wr   = (const float*)d_in[8];
    const float* Wo   = (const float*)d_in[9];
    float* out = (float*)d_out;

    size_t smem = (size_t)NSTAGE * STAGE_BYTES;   // 64 KB
    cudaFuncSetAttribute(gemm_proj, cudaFuncAttributeMaxDynamicSharedMemorySize,
                         (int)smem);
    cudaFuncSetAttribute(gemm_out, cudaFuncAttributeMaxDynamicSharedMemorySize,
                         (int)smem);

    // 0. convert weights to fp16
    {
        int n4 = 4 * (DDIM * CDIM) / 4;
        round_weights<<<n4 / 256, 256>>>(Wk, Wv, Wr, Wo);
    }

    // 1. mixing
    {
        int n = MTOT * CDIM / 4;
        mix_kernel<<<n / 256, 256>>>(x, tmk, tmv, tmr);
    }

    // 2. K/V/R projections (merged launch)
    {
        dim3 grid(DDIM / 128, MTOT / 128, 3);
        gemm_proj<<<grid, 512, smem>>>(0);
    }

    // 3. wkv segmented scan
    {
        dim3 grid1(DDIM / 256, SSEG, BSZ);
        wkv_pass1<<<grid1, 256>>>(td);
        wkv_scan<<<(BSZ * DDIM) / 256, 256>>>(td);
        wkv_pass2<<<grid1, 256>>>(td, tf);
    }

    // 4. output projection
    {
        dim3 grid(CDIM / 128, MTOT / 128, 1);
        gemm_out<<<grid, 512, smem>>>(out);
    }
}